// round 1
// baseline (speedup 1.0000x reference)
#include <cuda_runtime.h>
#include <math.h>

#define D_    1024
#define DL_   1024
#define DH_   2048
#define NL_   64
#define H_    16
#define E_    8
#define B_    2
#define T_    2048
#define NTOK  (B_*T_)      /* 4096 */
#define HALF_ 32
#define SLOTS (NTOK*2)     /* 8192 */

// ----------------------------- scratch (device globals, no allocs) -----------
__device__ float g_Lq[NL_*DL_];
__device__ float g_K [NTOK*DL_];
__device__ float g_V [NTOK*DL_];
__device__ float g_Qx[NTOK*DL_];
__device__ float g_z [B_*NL_*DL_];
__device__ float g_Ql[B_*NL_*DL_];
__device__ float g_Kl[B_*NL_*DL_];
__device__ float g_Vl[B_*NL_*DL_];
__device__ float g_z2[B_*NL_*DL_];
__device__ float g_Kz[B_*NL_*DL_];
__device__ float g_Vz[B_*NL_*DL_];
__device__ float g_xl[NTOK*DL_];
__device__ float g_attnout[NTOK*D_];
__device__ float g_x1[NTOK*D_];
__device__ float g_moe[NTOK*D_];
__device__ float g_x2[NTOK*D_];
__device__ float g_lin[NTOK*D_];
__device__ float g_h[(size_t)SLOTS*DH_];   // 64 MB hidden buffer
__device__ int   g_counts[E_];
__device__ int   g_offsets[E_];
__device__ int   g_cursor[E_];
__device__ int   g_slot_token[SLOTS];
__device__ float g_slot_gate[SLOTS];
__device__ int   g_topi[NTOK*2];
__device__ float g_gate[NTOK*2];

// ----------------------------- generic fp32 tiled GEMM -----------------------
// C[M,N] = A[M,K] @ B[K,N]; requires N%64==0, K%16==0 (true for all calls).
__global__ void gemm64_kernel(const float* __restrict__ A, const float* __restrict__ B,
                              float* __restrict__ C, int M, int N, int K) {
    __shared__ float As[16][64];
    __shared__ float Bs[16][64];
    const int tile_m = blockIdx.x * 64;
    const int tile_n = blockIdx.y * 64;
    const int tid = threadIdx.x;
    const int tx = tid & 15, ty = tid >> 4;
    float acc[4][4] = {};
    for (int k0 = 0; k0 < K; k0 += 16) {
        for (int i = tid; i < 64*16; i += 256) {
            int m = i >> 4, k = i & 15;
            int gm = tile_m + m;
            As[k][m] = (gm < M) ? A[(size_t)gm * K + k0 + k] : 0.f;
        }
        for (int i = tid; i < 16*64; i += 256) {
            int k = i >> 6, n = i & 63;
            Bs[k][n] = B[(size_t)(k0 + k) * N + tile_n + n];
        }
        __syncthreads();
        #pragma unroll
        for (int kk = 0; kk < 16; kk++) {
            float a[4], b[4];
            #pragma unroll
            for (int i = 0; i < 4; i++) a[i] = As[kk][ty*4 + i];
            #pragma unroll
            for (int j = 0; j < 4; j++) b[j] = Bs[kk][tx*4 + j];
            #pragma unroll
            for (int i = 0; i < 4; i++)
                #pragma unroll
                for (int j = 0; j < 4; j++)
                    acc[i][j] += a[i] * b[j];
        }
        __syncthreads();
    }
    #pragma unroll
    for (int i = 0; i < 4; i++) {
        int gm = tile_m + ty*4 + i;
        if (gm >= M) continue;
        #pragma unroll
        for (int j = 0; j < 4; j++)
            C[(size_t)gm * N + tile_n + tx*4 + j] = acc[i][j];
    }
}

// ----------------------------- RoPE ------------------------------------------
__global__ void rope_kernel(float* __restrict__ buf, const float* __restrict__ cosb,
                            const float* __restrict__ sinb) {
    int idx = blockIdx.x * blockDim.x + threadIdx.x;
    if (idx >= NTOK * H_ * HALF_) return;
    int j = idx & 31;
    int h = (idx >> 5) & 15;
    int r = idx >> 9;               // token row 0..NTOK-1
    int t = r % T_;
    float c = cosb[t * HALF_ + j];
    float s = sinb[t * HALF_ + j];
    size_t base = (size_t)r * DL_ + h * 64 + 2 * j;
    float x1 = buf[base], x2 = buf[base + 1];
    buf[base]     = x1 * c - x2 * s;
    buf[base + 1] = x1 * s + x2 * c;
}

// ----------------------------- small-key attention ---------------------------
// One block per (query q, head h, batch b), 64 threads. Keys <= 64.
// qbs/kbs/obs = row counts per batch in the respective buffers (qbs=0: shared Q).
__global__ void attn_kernel(const float* __restrict__ Q, int qbs,
                            const float* __restrict__ Ksrc, const float* __restrict__ Vsrc, int kbs,
                            float* __restrict__ Out, int obs, int causal) {
    int q = blockIdx.x, h = blockIdx.y, b = blockIdx.z;
    int tid = threadIdx.x;
    __shared__ float qv[64], sv[64], w[64];
    qv[tid] = Q[((size_t)(b * qbs + q)) * DL_ + h * 64 + tid];
    __syncthreads();
    int nk = causal ? (q + 1) : 64;
    if (nk > 64) nk = 64;
    bool act = tid < nk;
    float sc = -1e30f;
    if (act) {
        const float* kr = Ksrc + ((size_t)(b * kbs + tid)) * DL_ + h * 64;
        float dot = 0.f;
        #pragma unroll
        for (int d = 0; d < 64; d++) dot += qv[d] * kr[d];
        sc = dot * 0.125f;
    }
    sv[tid] = sc;
    __syncthreads();
    float mx = -1e30f;
    for (int j = 0; j < nk; j++) mx = fmaxf(mx, sv[j]);
    w[tid] = act ? expf(sc - mx) : 0.f;
    __syncthreads();
    float sum = 0.f;
    for (int j = 0; j < nk; j++) sum += w[j];
    float o = 0.f;
    for (int j = 0; j < nk; j++)
        o += w[j] * Vsrc[((size_t)(b * kbs + j)) * DL_ + h * 64 + tid];
    Out[((size_t)(b * obs + q)) * DL_ + h * 64 + tid] = o / sum;
}

// ----------------------------- LayerNorm(+residual+bias) ---------------------
// out[row] = g*(src-mean)/(std_ddof1 + 1e-6) + beta + add [+ bias]
__global__ void add_ln_kernel(const float* __restrict__ src, const float* __restrict__ addv,
                              const float* __restrict__ g, const float* __restrict__ bt,
                              const float* __restrict__ bias, float* __restrict__ out) {
    int row = blockIdx.x;
    int tid = threadIdx.x;
    const float* x = src + (size_t)row * D_;
    float v[4];
    #pragma unroll
    for (int i = 0; i < 4; i++) v[i] = x[tid + i * 256];
    __shared__ float red[256];
    float s = v[0] + v[1] + v[2] + v[3];
    red[tid] = s; __syncthreads();
    for (int o = 128; o > 0; o >>= 1) { if (tid < o) red[tid] += red[tid + o]; __syncthreads(); }
    float mean = red[0] * (1.f / 1024.f);
    __syncthreads();
    float d0 = v[0]-mean, d1 = v[1]-mean, d2 = v[2]-mean, d3 = v[3]-mean;
    red[tid] = d0*d0 + d1*d1 + d2*d2 + d3*d3; __syncthreads();
    for (int o = 128; o > 0; o >>= 1) { if (tid < o) red[tid] += red[tid + o]; __syncthreads(); }
    float stdv = sqrtf(red[0] * (1.f / 1023.f));
    float inv = 1.f / (stdv + 1e-6f);
    #pragma unroll
    for (int i = 0; i < 4; i++) {
        int c = tid + i * 256;
        float r = g[c] * (v[i] - mean) * inv + bt[c] + addv[(size_t)row * D_ + c];
        if (bias) r += bias[c];
        out[(size_t)row * D_ + c] = r;
    }
}

// ----------------------------- router + routing ------------------------------
__global__ void router_kernel(const float* __restrict__ X, const float* __restrict__ Wr,
                              const float* __restrict__ br) {
    int n = blockIdx.x;
    int tid = threadIdx.x;
    int wrp = tid >> 5, lane = tid & 31;
    const float* xr = X + (size_t)n * D_;
    float p = 0.f;
    for (int d = lane; d < D_; d += 32) p += xr[d] * Wr[d * E_ + wrp];
    #pragma unroll
    for (int o = 16; o > 0; o >>= 1) p += __shfl_down_sync(0xffffffffu, p, o);
    __shared__ float lg[E_];
    if (lane == 0) lg[wrp] = p + br[wrp];
    __syncthreads();
    if (tid == 0) {
        int i0 = 0; float v0 = lg[0];
        for (int e = 1; e < E_; e++) if (lg[e] > v0) { v0 = lg[e]; i0 = e; }
        int i1 = -1; float v1 = -1e30f;
        for (int e = 0; e < E_; e++) if (e != i0 && lg[e] > v1) { v1 = lg[e]; i1 = e; }
        float e1 = expf(v1 - v0);
        float p0 = 1.f / (1.f + e1);
        float p1 = e1 / (1.f + e1);
        g_topi[n*2] = i0;  g_topi[n*2+1] = i1;
        g_gate[n*2] = p0;  g_gate[n*2+1] = p1;
        atomicAdd(&g_counts[i0], 1);
        atomicAdd(&g_counts[i1], 1);
    }
}

__global__ void scan_kernel() {
    if (threadIdx.x == 0 && blockIdx.x == 0) {
        int acc = 0;
        for (int e = 0; e < E_; e++) { g_offsets[e] = acc; acc += g_counts[e]; g_cursor[e] = 0; }
    }
}

__global__ void scatter_kernel() {
    int n = blockIdx.x * blockDim.x + threadIdx.x;
    if (n >= NTOK) return;
    #pragma unroll
    for (int k = 0; k < 2; k++) {
        int e = g_topi[n*2 + k];
        int pos = atomicAdd(&g_cursor[e], 1);
        int s = g_offsets[e] + pos;
        g_slot_token[s] = n;
        g_slot_gate[s]  = g_gate[n*2 + k];
    }
}

// ----------------------------- MoE grouped GEMMs -----------------------------
// Stage 1: h = (Xg @ We_w[e]) * silu(Xg @ We_v[e]), gathered rows.
__global__ void moe_gemm1_kernel(const float* __restrict__ X, const float* __restrict__ Ww,
                                 const float* __restrict__ Wv) {
    int e = blockIdx.z;
    int cnt = g_counts[e];
    int tile_m = blockIdx.x * 64;
    if (tile_m >= cnt) return;
    int base = g_offsets[e];
    int tile_n = blockIdx.y * 64;
    const float* Bw = Ww + (size_t)e * D_ * DH_;
    const float* Bv = Wv + (size_t)e * D_ * DH_;
    __shared__ float As[16][64];
    __shared__ float Bws[16][64];
    __shared__ float Bvs[16][64];
    __shared__ int rowtok[64];
    int tid = threadIdx.x;
    if (tid < 64) {
        int m = tile_m + tid;
        rowtok[tid] = (m < cnt) ? g_slot_token[base + m] : -1;
    }
    __syncthreads();
    int tx = tid & 15, ty = tid >> 4;
    float accA[4][4] = {}, accB[4][4] = {};
    for (int k0 = 0; k0 < D_; k0 += 16) {
        for (int i = tid; i < 64*16; i += 256) {
            int m = i >> 4, k = i & 15;
            int tok = rowtok[m];
            As[k][m] = (tok >= 0) ? X[(size_t)tok * D_ + k0 + k] : 0.f;
        }
        for (int i = tid; i < 16*64; i += 256) {
            int k = i >> 6, n = i & 63;
            Bws[k][n] = Bw[(size_t)(k0 + k) * DH_ + tile_n + n];
            Bvs[k][n] = Bv[(size_t)(k0 + k) * DH_ + tile_n + n];
        }
        __syncthreads();
        #pragma unroll
        for (int kk = 0; kk < 16; kk++) {
            float a[4];
            #pragma unroll
            for (int i = 0; i < 4; i++) a[i] = As[kk][ty*4 + i];
            #pragma unroll
            for (int j = 0; j < 4; j++) {
                float bw = Bws[kk][tx*4 + j];
                float bv = Bvs[kk][tx*4 + j];
                #pragma unroll
                for (int i = 0; i < 4; i++) {
                    accA[i][j] += a[i] * bw;
                    accB[i][j] += a[i] * bv;
                }
            }
        }
        __syncthreads();
    }
    #pragma unroll
    for (int i = 0; i < 4; i++) {
        int m = tile_m + ty*4 + i;
        if (m >= cnt) continue;
        #pragma unroll
        for (int j = 0; j < 4; j++) {
            float a = accA[i][j], bval = accB[i][j];
            float sg = 1.f / (1.f + expf(-bval));
            g_h[(size_t)(base + m) * DH_ + tile_n + tx*4 + j] = a * (bval * sg);
        }
    }
}

// Stage 2: moe_out[token] += gate * (h_row @ We_o[e])
__global__ void moe_gemm2_kernel(const float* __restrict__ Wo, float* __restrict__ OutAcc) {
    int e = blockIdx.z;
    int cnt = g_counts[e];
    int tile_m = blockIdx.x * 64;
    if (tile_m >= cnt) return;
    int base = g_offsets[e];
    int tile_n = blockIdx.y * 64;
    const float* Bm = Wo + (size_t)e * DH_ * D_;
    __shared__ float As[16][64];
    __shared__ float Bs[16][64];
    __shared__ int   rowtok[64];
    __shared__ float rowg[64];
    int tid = threadIdx.x;
    if (tid < 64) {
        int m = tile_m + tid;
        if (m < cnt) { rowtok[tid] = g_slot_token[base + m]; rowg[tid] = g_slot_gate[base + m]; }
        else         { rowtok[tid] = -1; rowg[tid] = 0.f; }
    }
    __syncthreads();
    int tx = tid & 15, ty = tid >> 4;
    float acc[4][4] = {};
    for (int k0 = 0; k0 < DH_; k0 += 16) {
        for (int i = tid; i < 64*16; i += 256) {
            int m = i >> 4, k = i & 15;
            As[k][m] = (rowtok[m] >= 0) ? g_h[(size_t)(base + tile_m + m) * DH_ + k0 + k] : 0.f;
        }
        for (int i = tid; i < 16*64; i += 256) {
            int k = i >> 6, n = i & 63;
            Bs[k][n] = Bm[(size_t)(k0 + k) * D_ + tile_n + n];
        }
        __syncthreads();
        #pragma unroll
        for (int kk = 0; kk < 16; kk++) {
            float a[4], b[4];
            #pragma unroll
            for (int i = 0; i < 4; i++) a[i] = As[kk][ty*4 + i];
            #pragma unroll
            for (int j = 0; j < 4; j++) b[j] = Bs[kk][tx*4 + j];
            #pragma unroll
            for (int i = 0; i < 4; i++)
                #pragma unroll
                for (int j = 0; j < 4; j++)
                    acc[i][j] += a[i] * b[j];
        }
        __syncthreads();
    }
    #pragma unroll
    for (int i = 0; i < 4; i++) {
        int ml = ty*4 + i;
        int tok = rowtok[ml];
        if (tok < 0) continue;
        float gv = rowg[ml];
        #pragma unroll
        for (int j = 0; j < 4; j++)
            atomicAdd(&OutAcc[(size_t)tok * D_ + tile_n + tx*4 + j], gv * acc[i][j]);
    }
}

// ----------------------------- host ------------------------------------------
static inline void gemm(const float* A, const float* B, float* C, int M, int N, int K) {
    dim3 grid((M + 63) / 64, N / 64);
    gemm64_kernel<<<grid, 256>>>(A, B, C, M, N, K);
}

extern "C" void kernel_launch(void* const* d_in, const int* in_sizes, int n_in,
                              void* d_out, int out_size) {
    const float* x        = (const float*)d_in[0];
    const float* cosb     = (const float*)d_in[1];
    const float* sinb     = (const float*)d_in[2];
    const float* ln1g     = (const float*)d_in[3];
    const float* ln1b     = (const float*)d_in[4];
    const float* ln2g     = (const float*)d_in[5];
    const float* ln2b     = (const float*)d_in[6];
    const float* ln3g     = (const float*)d_in[7];
    const float* ln3b     = (const float*)d_in[8];
    const float* Lat      = (const float*)d_in[9];
    const float* wq_lat   = (const float*)d_in[10];
    const float* wk_in    = (const float*)d_in[11];
    const float* wv_in    = (const float*)d_in[12];
    const float* wq_in    = (const float*)d_in[13];
    const float* wk_lat   = (const float*)d_in[14];
    const float* wv_lat   = (const float*)d_in[15];
    const float* w_out    = (const float*)d_in[16];
    const float* router_w = (const float*)d_in[17];
    const float* router_b = (const float*)d_in[18];
    const float* We_w     = (const float*)d_in[19];
    const float* We_v     = (const float*)d_in[20];
    const float* We_o     = (const float*)d_in[21];
    const float* lin_w    = (const float*)d_in[22];
    const float* lin_b    = (const float*)d_in[23];
    float* out = (float*)d_out;

    float *pLq, *pK, *pV, *pQx, *pz, *pQl, *pKl, *pVl, *pz2, *pKz, *pVz;
    float *pxl, *pattn, *px1, *pmoe, *px2, *plin;
    int *pcounts;
    cudaGetSymbolAddress((void**)&pLq,  g_Lq);
    cudaGetSymbolAddress((void**)&pK,   g_K);
    cudaGetSymbolAddress((void**)&pV,   g_V);
    cudaGetSymbolAddress((void**)&pQx,  g_Qx);
    cudaGetSymbolAddress((void**)&pz,   g_z);
    cudaGetSymbolAddress((void**)&pQl,  g_Ql);
    cudaGetSymbolAddress((void**)&pKl,  g_Kl);
    cudaGetSymbolAddress((void**)&pVl,  g_Vl);
    cudaGetSymbolAddress((void**)&pz2,  g_z2);
    cudaGetSymbolAddress((void**)&pKz,  g_Kz);
    cudaGetSymbolAddress((void**)&pVz,  g_Vz);
    cudaGetSymbolAddress((void**)&pxl,  g_xl);
    cudaGetSymbolAddress((void**)&pattn,g_attnout);
    cudaGetSymbolAddress((void**)&px1,  g_x1);
    cudaGetSymbolAddress((void**)&pmoe, g_moe);
    cudaGetSymbolAddress((void**)&px2,  g_x2);
    cudaGetSymbolAddress((void**)&plin, g_lin);
    cudaGetSymbolAddress((void**)&pcounts, g_counts);

    // ---- attention pipeline ----
    gemm(Lat, wq_lat, pLq, NL_, DL_, DL_);          // latent queries (batch-shared)
    gemm(x, wk_in, pK,  NTOK, DL_, D_);
    gemm(x, wv_in, pV,  NTOK, DL_, D_);
    gemm(x, wq_in, pQx, NTOK, DL_, D_);

    int nrope = NTOK * H_ * HALF_;
    rope_kernel<<<(nrope + 255) / 256, 256>>>(pK,  cosb, sinb);
    rope_kernel<<<(nrope + 255) / 256, 256>>>(pQx, cosb, sinb);

    attn_kernel<<<dim3(NL_, H_, B_), 64>>>(pLq, 0,   pK,  pV,  T_,  pz,  NL_, 1); // causal 64xT
    gemm(pz, wq_lat, pQl, B_*NL_, DL_, DL_);
    gemm(pz, wk_lat, pKl, B_*NL_, DL_, DL_);
    gemm(pz, wv_lat, pVl, B_*NL_, DL_, DL_);
    attn_kernel<<<dim3(NL_, H_, B_), 64>>>(pQl, NL_, pKl, pVl, NL_, pz2, NL_, 0); // latent self
    gemm(pz2, wk_lat, pKz, B_*NL_, DL_, DL_);
    gemm(pz2, wv_lat, pVz, B_*NL_, DL_, DL_);
    attn_kernel<<<dim3(T_, H_, B_), 64>>>(pQx, T_,  pKz, pVz, NL_, pxl, T_,  0);  // cross back

    gemm(pxl, w_out, pattn, NTOK, D_, DL_);
    add_ln_kernel<<<NTOK, 256>>>(x, pattn, ln1g, ln1b, nullptr, px1);

    // ---- MoE (top-2 grouped GEMM) ----
    cudaMemsetAsync(pcounts, 0, E_ * sizeof(int), 0);
    router_kernel<<<NTOK, 256>>>(px1, router_w, router_b);
    scan_kernel<<<1, 32>>>();
    scatter_kernel<<<(NTOK + 255) / 256, 256>>>();
    moe_gemm1_kernel<<<dim3(64, DH_/64, E_), 256>>>(px1, We_w, We_v);
    cudaMemsetAsync(pmoe, 0, (size_t)NTOK * D_ * sizeof(float), 0);
    moe_gemm2_kernel<<<dim3(64, D_/64, E_), 256>>>(We_o, pmoe);
    add_ln_kernel<<<NTOK, 256>>>(px1, pmoe, ln2g, ln2b, nullptr, px2);

    // ---- final linear ----
    gemm(px2, lin_w, plin, NTOK, D_, D_);
    add_ln_kernel<<<NTOK, 256>>>(px2, plin, ln3g, ln3b, lin_b, out);
}

// round 3
// speedup vs baseline: 2.3547x; 2.3547x over previous
#include <cuda_runtime.h>
#include <cstdint>
#include <math.h>

#define D_    1024
#define DL_   1024
#define DH_   2048
#define NL_   64
#define H_    16
#define E_    8
#define B_    2
#define T_    2048
#define NTOK  (B_*T_)      /* 4096 */
#define HALF_ 32
#define SLOTS (NTOK*2)     /* 8192 */

// ----------------------------- scratch (device globals, no allocs) -----------
__device__ float g_Lq[NL_*DL_];
__device__ float g_K [NTOK*DL_];
__device__ float g_V [NTOK*DL_];
__device__ float g_Qx[NTOK*DL_];
__device__ float g_z [B_*NL_*DL_];
__device__ float g_Ql[B_*NL_*DL_];
__device__ float g_Kl[B_*NL_*DL_];
__device__ float g_Vl[B_*NL_*DL_];
__device__ float g_z2[B_*NL_*DL_];
__device__ float g_Kz[B_*NL_*DL_];
__device__ float g_Vz[B_*NL_*DL_];
__device__ float g_xl[NTOK*DL_];
__device__ float g_attnout[NTOK*D_];
__device__ float g_x1[NTOK*D_];
__device__ float g_moe[NTOK*D_];
__device__ float g_x2[NTOK*D_];
__device__ float g_lin[NTOK*D_];
__device__ float g_h [(size_t)SLOTS*DH_];   // hidden a (then swiglu result)
__device__ float g_hb[(size_t)SLOTS*DH_];   // hidden b
__device__ int   g_counts[E_];
__device__ int   g_offsets[E_];
__device__ int   g_cursor[E_];
__device__ int   g_slot_token[SLOTS];
__device__ float g_slot_gate[SLOTS];
__device__ int   g_topi[NTOK*2];
__device__ float g_gate[NTOK*2];

// ----------------------------- tf32 tensor-core GEMM -------------------------
__device__ __forceinline__ uint32_t f2tf(float f) {
    uint32_t u; asm("cvt.rna.tf32.f32 %0, %1;" : "=r"(u) : "f"(f)); return u;
}

__device__ __forceinline__ void mma_tf32(float* d, const uint32_t* a, const uint32_t* b) {
    asm volatile("mma.sync.aligned.m16n8k8.row.col.f32.tf32.tf32.f32 "
        "{%0,%1,%2,%3}, {%4,%5,%6,%7}, {%8,%9}, {%0,%1,%2,%3};\n"
        : "+f"(d[0]), "+f"(d[1]), "+f"(d[2]), "+f"(d[3])
        : "r"(a[0]), "r"(a[1]), "r"(a[2]), "r"(a[3]), "r"(b[0]), "r"(b[1]));
}

#define BM 128
#define BN 128
#define BK 32
#define ASTR 36    // As row stride (floats): bank map bijective per 8-lane group
#define BSTR 136   // Bs row stride (floats): bank map bijective per 8-lane group

// C[M,N] = A[M,K] @ B[K,N] in tf32 tensor cores, fp32 accumulate.
// expertMode: M=g_counts[z], base=g_offsets[z], B += z*K*N.
// gatherA: A row index = g_slot_token[base+m].
// scatterC: C[token] += gate * acc (atomic, exactly 2 adders per output elem).
__global__ void __launch_bounds__(256) tgemm_kernel(
    const float* __restrict__ A, const float* __restrict__ Bm, float* __restrict__ C,
    int M, int N, int K, int expertMode, int gatherA, int scatterC)
{
    __shared__ uint32_t As[BM * ASTR];
    __shared__ uint32_t Bs[BK * BSTR];
    __shared__ int   rIn[BM];
    __shared__ int   rOut[BM];
    __shared__ float rGate[BM];

    const int tid = threadIdx.x;
    int base = 0;
    if (expertMode) {
        int e = blockIdx.z;
        M = g_counts[e];
        base = g_offsets[e];
        Bm += (size_t)e * K * N;
    }
    const int tile_m = blockIdx.x * BM;
    if (tile_m >= M) return;
    const int tile_n = blockIdx.y * BN;

    if (tid < BM) {
        int m = tile_m + tid;
        if (m < M) {
            int slot = base + m;
            rIn[tid]   = gatherA  ? g_slot_token[slot] : (expertMode ? slot : m);
            rOut[tid]  = scatterC ? g_slot_token[slot] : (expertMode ? slot : m);
            rGate[tid] = scatterC ? g_slot_gate[slot] : 1.f;
        } else { rIn[tid] = -1; rOut[tid] = -1; rGate[tid] = 0.f; }
    }
    __syncthreads();

    // staging: 256 threads cover A tile 128x32 (2 thr/row, 16 floats each)
    //          and B tile 32x128 (8 thr/row, 16 floats each)
    const int ar_ = tid >> 1;
    const int ac_ = (tid & 1) * 16;
    const int bk_ = tid >> 3;
    const int bn_ = (tid & 7) * 16;

    float4 pa[4], pb[4];
    {
        int ar = rIn[ar_];
        const float4* ap = (const float4*)(A + (size_t)(ar < 0 ? 0 : ar) * K + ac_);
        #pragma unroll
        for (int j = 0; j < 4; j++)
            pa[j] = (ar >= 0) ? __ldg(ap + j) : make_float4(0.f,0.f,0.f,0.f);
        const float4* bp = (const float4*)(Bm + (size_t)bk_ * N + tile_n + bn_);
        #pragma unroll
        for (int j = 0; j < 4; j++) pb[j] = __ldg(bp + j);
    }

    const int lane = tid & 31;
    const int wid  = tid >> 5;
    const int wm = (wid >> 2) * 64;
    const int wn = (wid & 3) * 32;
    const int gid = lane >> 2, tig = lane & 3;

    float acc[4][4][4];
    #pragma unroll
    for (int i = 0; i < 4; i++)
        #pragma unroll
        for (int j = 0; j < 4; j++)
            #pragma unroll
            for (int q = 0; q < 4; q++) acc[i][j][q] = 0.f;

    const int nkt = K / BK;
    for (int kt = 0; kt < nkt; kt++) {
        // convert + store staged tile to smem
        {
            uint32_t* da = &As[ar_ * ASTR + ac_];
            #pragma unroll
            for (int j = 0; j < 4; j++) {
                uint4 v;
                v.x = f2tf(pa[j].x); v.y = f2tf(pa[j].y);
                v.z = f2tf(pa[j].z); v.w = f2tf(pa[j].w);
                *(uint4*)(da + 4*j) = v;
            }
            uint32_t* db = &Bs[bk_ * BSTR + bn_];
            #pragma unroll
            for (int j = 0; j < 4; j++) {
                uint4 v;
                v.x = f2tf(pb[j].x); v.y = f2tf(pb[j].y);
                v.z = f2tf(pb[j].z); v.w = f2tf(pb[j].w);
                *(uint4*)(db + 4*j) = v;
            }
        }
        __syncthreads();

        // prefetch next ktile while computing this one
        if (kt + 1 < nkt) {
            int k0 = (kt + 1) * BK;
            int ar = rIn[ar_];
            const float4* ap = (const float4*)(A + (size_t)(ar < 0 ? 0 : ar) * K + k0 + ac_);
            #pragma unroll
            for (int j = 0; j < 4; j++)
                pa[j] = (ar >= 0) ? __ldg(ap + j) : make_float4(0.f,0.f,0.f,0.f);
            const float4* bp = (const float4*)(Bm + (size_t)(k0 + bk_) * N + tile_n + bn_);
            #pragma unroll
            for (int j = 0; j < 4; j++) pb[j] = __ldg(bp + j);
        }

        #pragma unroll
        for (int ks = 0; ks < 4; ks++) {
            const int k8 = ks * 8;
            uint32_t af[4][4], bf[4][2];
            #pragma unroll
            for (int mi = 0; mi < 4; mi++) {
                int m0 = wm + mi*16 + gid;
                af[mi][0] = As[(m0    ) * ASTR + k8 + tig];
                af[mi][1] = As[(m0 + 8) * ASTR + k8 + tig];
                af[mi][2] = As[(m0    ) * ASTR + k8 + tig + 4];
                af[mi][3] = As[(m0 + 8) * ASTR + k8 + tig + 4];
            }
            #pragma unroll
            for (int ni = 0; ni < 4; ni++) {
                int n0 = wn + ni*8 + gid;
                bf[ni][0] = Bs[(k8 + tig    ) * BSTR + n0];
                bf[ni][1] = Bs[(k8 + tig + 4) * BSTR + n0];
            }
            #pragma unroll
            for (int mi = 0; mi < 4; mi++)
                #pragma unroll
                for (int ni = 0; ni < 4; ni++)
                    mma_tf32(acc[mi][ni], af[mi], bf[ni]);
        }
        __syncthreads();
    }

    // epilogue
    #pragma unroll
    for (int mi = 0; mi < 4; mi++) {
        int rl0 = wm + mi*16 + gid;
        int rl1 = rl0 + 8;
        int o0 = rOut[rl0], o1 = rOut[rl1];
        float g0 = rGate[rl0], g1 = rGate[rl1];
        #pragma unroll
        for (int ni = 0; ni < 4; ni++) {
            int c = tile_n + wn + ni*8 + tig*2;
            if (scatterC) {
                if (o0 >= 0) {
                    atomicAdd(&C[(size_t)o0*N + c],     g0*acc[mi][ni][0]);
                    atomicAdd(&C[(size_t)o0*N + c + 1], g0*acc[mi][ni][1]);
                }
                if (o1 >= 0) {
                    atomicAdd(&C[(size_t)o1*N + c],     g1*acc[mi][ni][2]);
                    atomicAdd(&C[(size_t)o1*N + c + 1], g1*acc[mi][ni][3]);
                }
            } else {
                if (o0 >= 0) *(float2*)&C[(size_t)o0*N + c] = make_float2(acc[mi][ni][0], acc[mi][ni][1]);
                if (o1 >= 0) *(float2*)&C[(size_t)o1*N + c] = make_float2(acc[mi][ni][2], acc[mi][ni][3]);
            }
        }
    }
}

// ----------------------------- SwiGLU elementwise ----------------------------
__global__ void swiglu_kernel(float4* __restrict__ ha, const float4* __restrict__ hb) {
    size_t i = (size_t)blockIdx.x * blockDim.x + threadIdx.x;
    float4 a = ha[i];
    float4 b = hb[i];
    a.x *= b.x / (1.f + __expf(-b.x));
    a.y *= b.y / (1.f + __expf(-b.y));
    a.z *= b.z / (1.f + __expf(-b.z));
    a.w *= b.w / (1.f + __expf(-b.w));
    ha[i] = a;
}

// ----------------------------- RoPE ------------------------------------------
__global__ void rope_kernel(float* __restrict__ buf, const float* __restrict__ cosb,
                            const float* __restrict__ sinb) {
    int idx = blockIdx.x * blockDim.x + threadIdx.x;
    if (idx >= NTOK * H_ * HALF_) return;
    int j = idx & 31;
    int h = (idx >> 5) & 15;
    int r = idx >> 9;
    int t = r % T_;
    float c = cosb[t * HALF_ + j];
    float s = sinb[t * HALF_ + j];
    size_t base = (size_t)r * DL_ + h * 64 + 2 * j;
    float x1 = buf[base], x2 = buf[base + 1];
    buf[base]     = x1 * c - x2 * s;
    buf[base + 1] = x1 * s + x2 * c;
}

// ----------------------------- small-key attention ---------------------------
__global__ void attn_kernel(const float* __restrict__ Q, int qbs,
                            const float* __restrict__ Ksrc, const float* __restrict__ Vsrc, int kbs,
                            float* __restrict__ Out, int obs, int causal) {
    int q = blockIdx.x, h = blockIdx.y, b = blockIdx.z;
    int tid = threadIdx.x;
    __shared__ float qv[64], sv[64], w[64];
    qv[tid] = Q[((size_t)(b * qbs + q)) * DL_ + h * 64 + tid];
    __syncthreads();
    int nk = causal ? (q + 1) : 64;
    if (nk > 64) nk = 64;
    bool act = tid < nk;
    float sc = -1e30f;
    if (act) {
        const float* kr = Ksrc + ((size_t)(b * kbs + tid)) * DL_ + h * 64;
        float dot = 0.f;
        #pragma unroll
        for (int d = 0; d < 64; d++) dot += qv[d] * kr[d];
        sc = dot * 0.125f;
    }
    sv[tid] = sc;
    __syncthreads();
    float mx = -1e30f;
    for (int j = 0; j < nk; j++) mx = fmaxf(mx, sv[j]);
    w[tid] = act ? expf(sc - mx) : 0.f;
    __syncthreads();
    float sum = 0.f;
    for (int j = 0; j < nk; j++) sum += w[j];
    float o = 0.f;
    for (int j = 0; j < nk; j++)
        o += w[j] * Vsrc[((size_t)(b * kbs + j)) * DL_ + h * 64 + tid];
    Out[((size_t)(b * obs + q)) * DL_ + h * 64 + tid] = o / sum;
}

// ----------------------------- LayerNorm(+residual+bias) ---------------------
__global__ void add_ln_kernel(const float* __restrict__ src, const float* __restrict__ addv,
                              const float* __restrict__ g, const float* __restrict__ bt,
                              const float* __restrict__ bias, float* __restrict__ out) {
    int row = blockIdx.x;
    int tid = threadIdx.x;
    const float* x = src + (size_t)row * D_;
    float v[4];
    #pragma unroll
    for (int i = 0; i < 4; i++) v[i] = x[tid + i * 256];
    __shared__ float red[256];
    float s = v[0] + v[1] + v[2] + v[3];
    red[tid] = s; __syncthreads();
    for (int o = 128; o > 0; o >>= 1) { if (tid < o) red[tid] += red[tid + o]; __syncthreads(); }
    float mean = red[0] * (1.f / 1024.f);
    __syncthreads();
    float d0 = v[0]-mean, d1 = v[1]-mean, d2 = v[2]-mean, d3 = v[3]-mean;
    red[tid] = d0*d0 + d1*d1 + d2*d2 + d3*d3; __syncthreads();
    for (int o = 128; o > 0; o >>= 1) { if (tid < o) red[tid] += red[tid + o]; __syncthreads(); }
    float stdv = sqrtf(red[0] * (1.f / 1023.f));
    float inv = 1.f / (stdv + 1e-6f);
    #pragma unroll
    for (int i = 0; i < 4; i++) {
        int c = tid + i * 256;
        float r = g[c] * (v[i] - mean) * inv + bt[c] + addv[(size_t)row * D_ + c];
        if (bias) r += bias[c];
        out[(size_t)row * D_ + c] = r;
    }
}

// ----------------------------- router + routing ------------------------------
__global__ void router_kernel(const float* __restrict__ X, const float* __restrict__ Wr,
                              const float* __restrict__ br) {
    int n = blockIdx.x;
    int tid = threadIdx.x;
    int wrp = tid >> 5, lane = tid & 31;
    const float* xr = X + (size_t)n * D_;
    float p = 0.f;
    for (int d = lane; d < D_; d += 32) p += xr[d] * Wr[d * E_ + wrp];
    #pragma unroll
    for (int o = 16; o > 0; o >>= 1) p += __shfl_down_sync(0xffffffffu, p, o);
    __shared__ float lg[E_];
    if (lane == 0) lg[wrp] = p + br[wrp];
    __syncthreads();
    if (tid == 0) {
        int i0 = 0; float v0 = lg[0];
        for (int e = 1; e < E_; e++) if (lg[e] > v0) { v0 = lg[e]; i0 = e; }
        int i1 = -1; float v1 = -1e30f;
        for (int e = 0; e < E_; e++) if (e != i0 && lg[e] > v1) { v1 = lg[e]; i1 = e; }
        float e1 = expf(v1 - v0);
        float p0 = 1.f / (1.f + e1);
        float p1 = e1 / (1.f + e1);
        g_topi[n*2] = i0;  g_topi[n*2+1] = i1;
        g_gate[n*2] = p0;  g_gate[n*2+1] = p1;
        atomicAdd(&g_counts[i0], 1);
        atomicAdd(&g_counts[i1], 1);
    }
}

__global__ void scan_kernel() {
    if (threadIdx.x == 0 && blockIdx.x == 0) {
        int acc = 0;
        for (int e = 0; e < E_; e++) { g_offsets[e] = acc; acc += g_counts[e]; g_cursor[e] = 0; }
    }
}

__global__ void scatter_kernel() {
    int n = blockIdx.x * blockDim.x + threadIdx.x;
    if (n >= NTOK) return;
    #pragma unroll
    for (int k = 0; k < 2; k++) {
        int e = g_topi[n*2 + k];
        int pos = atomicAdd(&g_cursor[e], 1);
        int s = g_offsets[e] + pos;
        g_slot_token[s] = n;
        g_slot_gate[s]  = g_gate[n*2 + k];
    }
}

// ----------------------------- host ------------------------------------------
static inline void tgemm(const float* A, const float* B, float* C, int M, int N, int K) {
    dim3 grid((M + BM - 1) / BM, N / BN, 1);
    tgemm_kernel<<<grid, 256>>>(A, B, C, M, N, K, 0, 0, 0);
}

extern "C" void kernel_launch(void* const* d_in, const int* in_sizes, int n_in,
                              void* d_out, int out_size) {
    const float* x        = (const float*)d_in[0];
    const float* cosb     = (const float*)d_in[1];
    const float* sinb     = (const float*)d_in[2];
    const float* ln1g     = (const float*)d_in[3];
    const float* ln1b     = (const float*)d_in[4];
    const float* ln2g     = (const float*)d_in[5];
    const float* ln2b     = (const float*)d_in[6];
    const float* ln3g     = (const float*)d_in[7];
    const float* ln3b     = (const float*)d_in[8];
    const float* Lat      = (const float*)d_in[9];
    const float* wq_lat   = (const float*)d_in[10];
    const float* wk_in    = (const float*)d_in[11];
    const float* wv_in    = (const float*)d_in[12];
    const float* wq_in    = (const float*)d_in[13];
    const float* wk_lat   = (const float*)d_in[14];
    const float* wv_lat   = (const float*)d_in[15];
    const float* w_out    = (const float*)d_in[16];
    const float* router_w = (const float*)d_in[17];
    const float* router_b = (const float*)d_in[18];
    const float* We_w     = (const float*)d_in[19];
    const float* We_v     = (const float*)d_in[20];
    const float* We_o     = (const float*)d_in[21];
    const float* lin_w    = (const float*)d_in[22];
    const float* lin_b    = (const float*)d_in[23];
    float* out = (float*)d_out;

    float *pLq, *pK, *pV, *pQx, *pz, *pQl, *pKl, *pVl, *pz2, *pKz, *pVz;
    float *pxl, *pattn, *px1, *pmoe, *px2, *plin, *ph, *phb;
    int *pcounts;
    cudaGetSymbolAddress((void**)&pLq,  g_Lq);
    cudaGetSymbolAddress((void**)&pK,   g_K);
    cudaGetSymbolAddress((void**)&pV,   g_V);
    cudaGetSymbolAddress((void**)&pQx,  g_Qx);
    cudaGetSymbolAddress((void**)&pz,   g_z);
    cudaGetSymbolAddress((void**)&pQl,  g_Ql);
    cudaGetSymbolAddress((void**)&pKl,  g_Kl);
    cudaGetSymbolAddress((void**)&pVl,  g_Vl);
    cudaGetSymbolAddress((void**)&pz2,  g_z2);
    cudaGetSymbolAddress((void**)&pKz,  g_Kz);
    cudaGetSymbolAddress((void**)&pVz,  g_Vz);
    cudaGetSymbolAddress((void**)&pxl,  g_xl);
    cudaGetSymbolAddress((void**)&pattn,g_attnout);
    cudaGetSymbolAddress((void**)&px1,  g_x1);
    cudaGetSymbolAddress((void**)&pmoe, g_moe);
    cudaGetSymbolAddress((void**)&px2,  g_x2);
    cudaGetSymbolAddress((void**)&plin, g_lin);
    cudaGetSymbolAddress((void**)&ph,   g_h);
    cudaGetSymbolAddress((void**)&phb,  g_hb);
    cudaGetSymbolAddress((void**)&pcounts, g_counts);

    // ---- attention pipeline ----
    tgemm(Lat, wq_lat, pLq, NL_, DL_, DL_);
    tgemm(x, wk_in, pK,  NTOK, DL_, D_);
    tgemm(x, wv_in, pV,  NTOK, DL_, D_);
    tgemm(x, wq_in, pQx, NTOK, DL_, D_);

    int nrope = NTOK * H_ * HALF_;
    rope_kernel<<<(nrope + 255) / 256, 256>>>(pK,  cosb, sinb);
    rope_kernel<<<(nrope + 255) / 256, 256>>>(pQx, cosb, sinb);

    attn_kernel<<<dim3(NL_, H_, B_), 64>>>(pLq, 0,   pK,  pV,  T_,  pz,  NL_, 1);
    tgemm(pz, wq_lat, pQl, B_*NL_, DL_, DL_);
    tgemm(pz, wk_lat, pKl, B_*NL_, DL_, DL_);
    tgemm(pz, wv_lat, pVl, B_*NL_, DL_, DL_);
    attn_kernel<<<dim3(NL_, H_, B_), 64>>>(pQl, NL_, pKl, pVl, NL_, pz2, NL_, 0);
    tgemm(pz2, wk_lat, pKz, B_*NL_, DL_, DL_);
    tgemm(pz2, wv_lat, pVz, B_*NL_, DL_, DL_);
    attn_kernel<<<dim3(T_, H_, B_), 64>>>(pQx, T_,  pKz, pVz, NL_, pxl, T_,  0);

    tgemm(pxl, w_out, pattn, NTOK, D_, DL_);
    add_ln_kernel<<<NTOK, 256>>>(x, pattn, ln1g, ln1b, nullptr, px1);

    // ---- MoE (top-2 grouped GEMM, tf32) ----
    cudaMemsetAsync(pcounts, 0, E_ * sizeof(int), 0);
    router_kernel<<<NTOK, 256>>>(px1, router_w, router_b);
    scan_kernel<<<1, 32>>>();
    scatter_kernel<<<(NTOK + 255) / 256, 256>>>();

    tgemm_kernel<<<dim3(SLOTS/BM, DH_/BN, E_), 256>>>(px1, We_w, ph,  0, DH_, D_, 1, 1, 0);
    tgemm_kernel<<<dim3(SLOTS/BM, DH_/BN, E_), 256>>>(px1, We_v, phb, 0, DH_, D_, 1, 1, 0);
    swiglu_kernel<<<(SLOTS * (DH_/4)) / 256, 256>>>((float4*)ph, (const float4*)phb);

    cudaMemsetAsync(pmoe, 0, (size_t)NTOK * D_ * sizeof(float), 0);
    tgemm_kernel<<<dim3(SLOTS/BM, D_/BN, E_), 256>>>(ph, We_o, pmoe, 0, D_, DH_, 1, 0, 1);
    add_ln_kernel<<<NTOK, 256>>>(px1, pmoe, ln2g, ln2b, nullptr, px2);

    // ---- final linear ----
    tgemm(px2, lin_w, plin, NTOK, D_, D_);
    add_ln_kernel<<<NTOK, 256>>>(px2, plin, ln3g, ln3b, lin_b, out);
}

// round 4
// speedup vs baseline: 3.1582x; 1.3412x over previous
#include <cuda_runtime.h>
#include <cstdint>
#include <math.h>

#define D_    1024
#define DL_   1024
#define DH_   2048
#define NL_   64
#define H_    16
#define E_    8
#define B_    2
#define T_    2048
#define NTOK  (B_*T_)      /* 4096 */
#define HALF_ 32
#define SLOTS (NTOK*2)     /* 8192 */

// ----------------------------- scratch (device globals, no allocs) -----------
__device__ float g_Lq[NL_*DL_];
__device__ float g_K [NTOK*DL_];
__device__ float g_V [NTOK*DL_];
__device__ float g_Qx[NTOK*DL_];
__device__ float g_z [B_*NL_*DL_];
__device__ float g_Ql[B_*NL_*DL_];
__device__ float g_Kl[B_*NL_*DL_];
__device__ float g_Vl[B_*NL_*DL_];
__device__ float g_z2[B_*NL_*DL_];
__device__ float g_Kz[B_*NL_*DL_];
__device__ float g_Vz[B_*NL_*DL_];
__device__ float g_xl[NTOK*DL_];
__device__ float g_attnout[NTOK*D_];
__device__ float g_x1[NTOK*D_];
__device__ float g_moe[NTOK*D_];
__device__ float g_x2[NTOK*D_];
__device__ float g_lin[NTOK*D_];
__device__ float g_h [(size_t)SLOTS*DH_];
__device__ float g_hb[(size_t)SLOTS*DH_];
__device__ int   g_counts[E_];
__device__ int   g_offsets[E_];
__device__ int   g_cursor[E_];
__device__ int   g_slot_token[SLOTS];
__device__ float g_slot_gate[SLOTS];
__device__ int   g_topi[NTOK*2];
__device__ float g_gate[NTOK*2];

// ----------------------------- tf32 helpers ----------------------------------
__device__ __forceinline__ uint32_t f2tf(float f) {
    uint32_t u; asm("cvt.rna.tf32.f32 %0, %1;" : "=r"(u) : "f"(f)); return u;
}
__device__ __forceinline__ uint32_t f2tf_bits(uint32_t b) {
    uint32_t u; asm("cvt.rna.tf32.f32 %0, %1;" : "=r"(u) : "f"(__uint_as_float(b))); return u;
}
__device__ __forceinline__ void mma_tf32(float* d, const uint32_t* a, const uint32_t* b) {
    asm volatile("mma.sync.aligned.m16n8k8.row.col.f32.tf32.tf32.f32 "
        "{%0,%1,%2,%3}, {%4,%5,%6,%7}, {%8,%9}, {%0,%1,%2,%3};\n"
        : "+f"(d[0]), "+f"(d[1]), "+f"(d[2]), "+f"(d[3])
        : "r"(a[0]), "r"(a[1]), "r"(a[2]), "r"(a[3]), "r"(b[0]), "r"(b[1]));
}
__device__ __forceinline__ void ldmatrix4(uint32_t* r, uint32_t addr) {
    asm volatile("ldmatrix.sync.aligned.m8n8.x4.shared.b16 {%0,%1,%2,%3}, [%4];"
        : "=r"(r[0]), "=r"(r[1]), "=r"(r[2]), "=r"(r[3]) : "r"(addr));
}
__device__ __forceinline__ void cpasync16(uint32_t dst, const void* src) {
    asm volatile("cp.async.cg.shared.global [%0], [%1], 16;\n" :: "r"(dst), "l"(src));
}
__device__ __forceinline__ void cpcommit() {
    asm volatile("cp.async.commit_group;\n" ::: "memory");
}
__device__ __forceinline__ void cpwait2() {
    asm volatile("cp.async.wait_group 2;\n" ::: "memory");
}

#define BM 128
#define BN 256
#define BK 32
#define ASTR 36      // A smem row stride in words (128 rows x 32 k, padded)
#define BSTR 264     // B smem row stride in words (32 k rows x 256 n, padded)
#define AWORDS (BM*ASTR)              /* 4608 words = 18432 B */
#define BWORDS (BK*BSTR)              /* 8448 words = 33792 B */
#define STAGE_WORDS (AWORDS+BWORDS)   /* 13056 words = 52224 B */
#define STAGES 3
#define SMEM_TG (STAGES*STAGE_WORDS*4) /* 156672 B dynamic smem */

// C[M,N] = A[M,K] @ B[K,N], tf32 tensor cores, fp32 accumulate.
// expertMode: M=g_counts[z], base=g_offsets[z], B += z*K*N.
// gatherA: A row = g_slot_token[slot]; scatterC: C[token] += gate*acc (atomic).
__global__ void __launch_bounds__(256) tgemm_kernel(
    const float* __restrict__ A, const float* __restrict__ Bm, float* __restrict__ C,
    int M, int N, int K, int expertMode, int gatherA, int scatterC)
{
    extern __shared__ float dsm[];
    __shared__ int   rIn[BM];
    __shared__ int   rOut[BM];
    __shared__ float rGate[BM];

    const int tid = threadIdx.x;
    int base = 0;
    if (expertMode) {
        int e = blockIdx.z;
        M = g_counts[e];
        base = g_offsets[e];
        Bm += (size_t)e * K * N;
    }
    const int tile_m = blockIdx.x * BM;
    if (tile_m >= M) return;
    const int tile_n = blockIdx.y * BN;

    if (tid < BM) {
        int m = tile_m + tid;
        if (m < M) {
            int slot = base + m;
            rIn[tid]   = gatherA  ? g_slot_token[slot] : (expertMode ? slot : m);
            rOut[tid]  = scatterC ? g_slot_token[slot] : (expertMode ? slot : m);
            rGate[tid] = scatterC ? g_slot_gate[slot] : 1.f;
        } else { rIn[tid] = 0; rOut[tid] = -1; rGate[tid] = 0.f; }
    }
    __syncthreads();

    const uint32_t smem_u32 = (uint32_t)__cvta_generic_to_shared(dsm);

    const int lane = tid & 31;
    const int wid  = tid >> 5;
    const int wm = (wid >> 2) * 64;   // 2 warp rows
    const int wn = (wid & 3) * 64;    // 4 warp cols
    const int gid = lane >> 2, tig = lane & 3;

    // ldmatrix per-lane address part (within A stage): matrix j = lane/8, row r = lane%8
    const int lj = lane >> 3, lr = lane & 7;
    const uint32_t aLanePart = ((uint32_t)(wm + (lj & 1) * 8 + lr) * ASTR + (lj >> 1) * 4) * 4u;

    // cp.async assignments
    const int a_row = tid >> 3;            // +32 per i  (4 iters)
    const int a_kc  = (tid & 7) * 4;
    const int b_row = tid >> 6;            // +4 per i   (8 iters)
    const int b_nc  = (tid & 63) * 4;

    const int nkt = K / BK;

    // issue stage for ktile kt into buffer kt%STAGES
    auto issue = [&](int kt) {
        const int s = kt % STAGES;
        const int k0 = kt * BK;
        const uint32_t aBase = smem_u32 + s * (STAGE_WORDS * 4);
        const uint32_t bBase = aBase + AWORDS * 4;
        #pragma unroll
        for (int i = 0; i < 4; i++) {
            int row = a_row + i * 32;
            int ar = rIn[row];
            cpasync16(aBase + ((uint32_t)row * ASTR + a_kc) * 4u,
                      A + (size_t)ar * K + k0 + a_kc);
        }
        #pragma unroll
        for (int i = 0; i < 8; i++) {
            int row = b_row + i * 4;
            cpasync16(bBase + ((uint32_t)row * BSTR + b_nc) * 4u,
                      Bm + (size_t)(k0 + row) * N + tile_n + b_nc);
        }
    };

    float acc[4][8][4];
    #pragma unroll
    for (int i = 0; i < 4; i++)
        #pragma unroll
        for (int j = 0; j < 8; j++)
            #pragma unroll
            for (int q = 0; q < 4; q++) acc[i][j][q] = 0.f;

    issue(0); cpcommit();
    if (nkt > 1) issue(1); cpcommit();

    for (int kt = 0; kt < nkt; kt++) {
        if (kt + 2 < nkt) issue(kt + 2);
        cpcommit();
        cpwait2();
        __syncthreads();

        const int s = kt % STAGES;
        const uint32_t aBase = smem_u32 + s * (STAGE_WORDS * 4) + aLanePart;
        const float* Bs = dsm + s * STAGE_WORDS + AWORDS;

        #pragma unroll
        for (int ks = 0; ks < 4; ks++) {
            uint32_t af[4][4];
            #pragma unroll
            for (int mi = 0; mi < 4; mi++) {
                ldmatrix4(af[mi], aBase + mi * (16 * ASTR * 4) + ks * 32);
                #pragma unroll
                for (int q = 0; q < 4; q++) af[mi][q] = f2tf_bits(af[mi][q]);
            }
            uint32_t bf[8][2];
            #pragma unroll
            for (int ni = 0; ni < 8; ni++) {
                int idx = (ks * 8 + tig) * BSTR + wn + ni * 8 + gid;
                bf[ni][0] = f2tf(Bs[idx]);
                bf[ni][1] = f2tf(Bs[idx + 4 * BSTR]);
            }
            #pragma unroll
            for (int mi = 0; mi < 4; mi++)
                #pragma unroll
                for (int ni = 0; ni < 8; ni++)
                    mma_tf32(acc[mi][ni], af[mi], bf[ni]);
        }
        __syncthreads();
    }

    // epilogue
    #pragma unroll
    for (int mi = 0; mi < 4; mi++) {
        int rl0 = wm + mi * 16 + gid;
        int rl1 = rl0 + 8;
        int o0 = rOut[rl0], o1 = rOut[rl1];
        float g0 = rGate[rl0], g1 = rGate[rl1];
        #pragma unroll
        for (int ni = 0; ni < 8; ni++) {
            int c = tile_n + wn + ni * 8 + tig * 2;
            if (scatterC) {
                if (o0 >= 0) {
                    atomicAdd(&C[(size_t)o0 * N + c],     g0 * acc[mi][ni][0]);
                    atomicAdd(&C[(size_t)o0 * N + c + 1], g0 * acc[mi][ni][1]);
                }
                if (o1 >= 0) {
                    atomicAdd(&C[(size_t)o1 * N + c],     g1 * acc[mi][ni][2]);
                    atomicAdd(&C[(size_t)o1 * N + c + 1], g1 * acc[mi][ni][3]);
                }
            } else {
                if (o0 >= 0) *(float2*)&C[(size_t)o0 * N + c] = make_float2(acc[mi][ni][0], acc[mi][ni][1]);
                if (o1 >= 0) *(float2*)&C[(size_t)o1 * N + c] = make_float2(acc[mi][ni][2], acc[mi][ni][3]);
            }
        }
    }
}

// ----------------------------- SwiGLU elementwise ----------------------------
__global__ void swiglu_kernel(float4* __restrict__ ha, const float4* __restrict__ hb) {
    size_t i = (size_t)blockIdx.x * blockDim.x + threadIdx.x;
    float4 a = ha[i];
    float4 b = hb[i];
    a.x *= b.x / (1.f + __expf(-b.x));
    a.y *= b.y / (1.f + __expf(-b.y));
    a.z *= b.z / (1.f + __expf(-b.z));
    a.w *= b.w / (1.f + __expf(-b.w));
    ha[i] = a;
}

// ----------------------------- RoPE ------------------------------------------
__global__ void rope_kernel(float* __restrict__ buf, const float* __restrict__ cosb,
                            const float* __restrict__ sinb) {
    int idx = blockIdx.x * blockDim.x + threadIdx.x;
    if (idx >= NTOK * H_ * HALF_) return;
    int j = idx & 31;
    int h = (idx >> 5) & 15;
    int r = idx >> 9;
    int t = r % T_;
    float c = cosb[t * HALF_ + j];
    float s = sinb[t * HALF_ + j];
    size_t base = (size_t)r * DL_ + h * 64 + 2 * j;
    float x1 = buf[base], x2 = buf[base + 1];
    buf[base]     = x1 * c - x2 * s;
    buf[base + 1] = x1 * s + x2 * c;
}

// ----------------------------- small-key attention ---------------------------
__global__ void attn_kernel(const float* __restrict__ Q, int qbs,
                            const float* __restrict__ Ksrc, const float* __restrict__ Vsrc, int kbs,
                            float* __restrict__ Out, int obs, int causal) {
    int q = blockIdx.x, h = blockIdx.y, b = blockIdx.z;
    int tid = threadIdx.x;
    __shared__ float qv[64], sv[64], w[64];
    qv[tid] = Q[((size_t)(b * qbs + q)) * DL_ + h * 64 + tid];
    __syncthreads();
    int nk = causal ? (q + 1) : 64;
    if (nk > 64) nk = 64;
    bool act = tid < nk;
    float sc = -1e30f;
    if (act) {
        const float* kr = Ksrc + ((size_t)(b * kbs + tid)) * DL_ + h * 64;
        float dot = 0.f;
        #pragma unroll
        for (int d = 0; d < 64; d++) dot += qv[d] * kr[d];
        sc = dot * 0.125f;
    }
    sv[tid] = sc;
    __syncthreads();
    float mx = -1e30f;
    for (int j = 0; j < nk; j++) mx = fmaxf(mx, sv[j]);
    w[tid] = act ? expf(sc - mx) : 0.f;
    __syncthreads();
    float sum = 0.f;
    for (int j = 0; j < nk; j++) sum += w[j];
    float o = 0.f;
    for (int j = 0; j < nk; j++)
        o += w[j] * Vsrc[((size_t)(b * kbs + j)) * DL_ + h * 64 + tid];
    Out[((size_t)(b * obs + q)) * DL_ + h * 64 + tid] = o / sum;
}

// ----------------------------- LayerNorm(+residual+bias) ---------------------
__global__ void add_ln_kernel(const float* __restrict__ src, const float* __restrict__ addv,
                              const float* __restrict__ g, const float* __restrict__ bt,
                              const float* __restrict__ bias, float* __restrict__ out) {
    int row = blockIdx.x;
    int tid = threadIdx.x;
    const float* x = src + (size_t)row * D_;
    float v[4];
    #pragma unroll
    for (int i = 0; i < 4; i++) v[i] = x[tid + i * 256];
    __shared__ float red[256];
    float s = v[0] + v[1] + v[2] + v[3];
    red[tid] = s; __syncthreads();
    for (int o = 128; o > 0; o >>= 1) { if (tid < o) red[tid] += red[tid + o]; __syncthreads(); }
    float mean = red[0] * (1.f / 1024.f);
    __syncthreads();
    float d0 = v[0]-mean, d1 = v[1]-mean, d2 = v[2]-mean, d3 = v[3]-mean;
    red[tid] = d0*d0 + d1*d1 + d2*d2 + d3*d3; __syncthreads();
    for (int o = 128; o > 0; o >>= 1) { if (tid < o) red[tid] += red[tid + o]; __syncthreads(); }
    float stdv = sqrtf(red[0] * (1.f / 1023.f));
    float inv = 1.f / (stdv + 1e-6f);
    #pragma unroll
    for (int i = 0; i < 4; i++) {
        int c = tid + i * 256;
        float r = g[c] * (v[i] - mean) * inv + bt[c] + addv[(size_t)row * D_ + c];
        if (bias) r += bias[c];
        out[(size_t)row * D_ + c] = r;
    }
}

// ----------------------------- router + routing ------------------------------
__global__ void router_kernel(const float* __restrict__ X, const float* __restrict__ Wr,
                              const float* __restrict__ br) {
    int n = blockIdx.x;
    int tid = threadIdx.x;
    int wrp = tid >> 5, lane = tid & 31;
    const float* xr = X + (size_t)n * D_;
    float p = 0.f;
    for (int d = lane; d < D_; d += 32) p += xr[d] * Wr[d * E_ + wrp];
    #pragma unroll
    for (int o = 16; o > 0; o >>= 1) p += __shfl_down_sync(0xffffffffu, p, o);
    __shared__ float lg[E_];
    if (lane == 0) lg[wrp] = p + br[wrp];
    __syncthreads();
    if (tid == 0) {
        int i0 = 0; float v0 = lg[0];
        for (int e = 1; e < E_; e++) if (lg[e] > v0) { v0 = lg[e]; i0 = e; }
        int i1 = -1; float v1 = -1e30f;
        for (int e = 0; e < E_; e++) if (e != i0 && lg[e] > v1) { v1 = lg[e]; i1 = e; }
        float e1 = expf(v1 - v0);
        float p0 = 1.f / (1.f + e1);
        float p1 = e1 / (1.f + e1);
        g_topi[n*2] = i0;  g_topi[n*2+1] = i1;
        g_gate[n*2] = p0;  g_gate[n*2+1] = p1;
        atomicAdd(&g_counts[i0], 1);
        atomicAdd(&g_counts[i1], 1);
    }
}

__global__ void scan_kernel() {
    if (threadIdx.x == 0 && blockIdx.x == 0) {
        int acc = 0;
        for (int e = 0; e < E_; e++) { g_offsets[e] = acc; acc += g_counts[e]; g_cursor[e] = 0; }
    }
}

__global__ void scatter_kernel() {
    int n = blockIdx.x * blockDim.x + threadIdx.x;
    if (n >= NTOK) return;
    #pragma unroll
    for (int k = 0; k < 2; k++) {
        int e = g_topi[n*2 + k];
        int pos = atomicAdd(&g_cursor[e], 1);
        int s = g_offsets[e] + pos;
        g_slot_token[s] = n;
        g_slot_gate[s]  = g_gate[n*2 + k];
    }
}

// ----------------------------- host ------------------------------------------
static inline void tgemm(const float* A, const float* B, float* C, int M, int N, int K) {
    dim3 grid((M + BM - 1) / BM, N / BN, 1);
    tgemm_kernel<<<grid, 256, SMEM_TG>>>(A, B, C, M, N, K, 0, 0, 0);
}

extern "C" void kernel_launch(void* const* d_in, const int* in_sizes, int n_in,
                              void* d_out, int out_size) {
    const float* x        = (const float*)d_in[0];
    const float* cosb     = (const float*)d_in[1];
    const float* sinb     = (const float*)d_in[2];
    const float* ln1g     = (const float*)d_in[3];
    const float* ln1b     = (const float*)d_in[4];
    const float* ln2g     = (const float*)d_in[5];
    const float* ln2b     = (const float*)d_in[6];
    const float* ln3g     = (const float*)d_in[7];
    const float* ln3b     = (const float*)d_in[8];
    const float* Lat      = (const float*)d_in[9];
    const float* wq_lat   = (const float*)d_in[10];
    const float* wk_in    = (const float*)d_in[11];
    const float* wv_in    = (const float*)d_in[12];
    const float* wq_in    = (const float*)d_in[13];
    const float* wk_lat   = (const float*)d_in[14];
    const float* wv_lat   = (const float*)d_in[15];
    const float* w_out    = (const float*)d_in[16];
    const float* router_w = (const float*)d_in[17];
    const float* router_b = (const float*)d_in[18];
    const float* We_w     = (const float*)d_in[19];
    const float* We_v     = (const float*)d_in[20];
    const float* We_o     = (const float*)d_in[21];
    const float* lin_w    = (const float*)d_in[22];
    const float* lin_b    = (const float*)d_in[23];
    float* out = (float*)d_out;

    static bool attrDone = false;
    if (!attrDone) {
        cudaFuncSetAttribute(tgemm_kernel, cudaFuncAttributeMaxDynamicSharedMemorySize, SMEM_TG);
        attrDone = true;
    }

    float *pLq, *pK, *pV, *pQx, *pz, *pQl, *pKl, *pVl, *pz2, *pKz, *pVz;
    float *pxl, *pattn, *px1, *pmoe, *px2, *plin, *ph, *phb;
    int *pcounts;
    cudaGetSymbolAddress((void**)&pLq,  g_Lq);
    cudaGetSymbolAddress((void**)&pK,   g_K);
    cudaGetSymbolAddress((void**)&pV,   g_V);
    cudaGetSymbolAddress((void**)&pQx,  g_Qx);
    cudaGetSymbolAddress((void**)&pz,   g_z);
    cudaGetSymbolAddress((void**)&pQl,  g_Ql);
    cudaGetSymbolAddress((void**)&pKl,  g_Kl);
    cudaGetSymbolAddress((void**)&pVl,  g_Vl);
    cudaGetSymbolAddress((void**)&pz2,  g_z2);
    cudaGetSymbolAddress((void**)&pKz,  g_Kz);
    cudaGetSymbolAddress((void**)&pVz,  g_Vz);
    cudaGetSymbolAddress((void**)&pxl,  g_xl);
    cudaGetSymbolAddress((void**)&pattn,g_attnout);
    cudaGetSymbolAddress((void**)&px1,  g_x1);
    cudaGetSymbolAddress((void**)&pmoe, g_moe);
    cudaGetSymbolAddress((void**)&px2,  g_x2);
    cudaGetSymbolAddress((void**)&plin, g_lin);
    cudaGetSymbolAddress((void**)&ph,   g_h);
    cudaGetSymbolAddress((void**)&phb,  g_hb);
    cudaGetSymbolAddress((void**)&pcounts, g_counts);

    // ---- attention pipeline ----
    tgemm(Lat, wq_lat, pLq, NL_, DL_, DL_);
    tgemm(x, wk_in, pK,  NTOK, DL_, D_);
    tgemm(x, wv_in, pV,  NTOK, DL_, D_);
    tgemm(x, wq_in, pQx, NTOK, DL_, D_);

    int nrope = NTOK * H_ * HALF_;
    rope_kernel<<<(nrope + 255) / 256, 256>>>(pK,  cosb, sinb);
    rope_kernel<<<(nrope + 255) / 256, 256>>>(pQx, cosb, sinb);

    attn_kernel<<<dim3(NL_, H_, B_), 64>>>(pLq, 0,   pK,  pV,  T_,  pz,  NL_, 1);
    tgemm(pz, wq_lat, pQl, B_*NL_, DL_, DL_);
    tgemm(pz, wk_lat, pKl, B_*NL_, DL_, DL_);
    tgemm(pz, wv_lat, pVl, B_*NL_, DL_, DL_);
    attn_kernel<<<dim3(NL_, H_, B_), 64>>>(pQl, NL_, pKl, pVl, NL_, pz2, NL_, 0);
    tgemm(pz2, wk_lat, pKz, B_*NL_, DL_, DL_);
    tgemm(pz2, wv_lat, pVz, B_*NL_, DL_, DL_);
    attn_kernel<<<dim3(T_, H_, B_), 64>>>(pQx, T_,  pKz, pVz, NL_, pxl, T_,  0);

    tgemm(pxl, w_out, pattn, NTOK, D_, DL_);
    add_ln_kernel<<<NTOK, 256>>>(x, pattn, ln1g, ln1b, nullptr, px1);

    // ---- MoE (top-2 grouped GEMM, tf32) ----
    cudaMemsetAsync(pcounts, 0, E_ * sizeof(int), 0);
    router_kernel<<<NTOK, 256>>>(px1, router_w, router_b);
    scan_kernel<<<1, 32>>>();
    scatter_kernel<<<(NTOK + 255) / 256, 256>>>();

    tgemm_kernel<<<dim3(SLOTS/BM, DH_/BN, E_), 256, SMEM_TG>>>(px1, We_w, ph,  0, DH_, D_, 1, 1, 0);
    tgemm_kernel<<<dim3(SLOTS/BM, DH_/BN, E_), 256, SMEM_TG>>>(px1, We_v, phb, 0, DH_, D_, 1, 1, 0);
    swiglu_kernel<<<(SLOTS * (DH_/4)) / 256, 256>>>((float4*)ph, (const float4*)phb);

    cudaMemsetAsync(pmoe, 0, (size_t)NTOK * D_ * sizeof(float), 0);
    tgemm_kernel<<<dim3(SLOTS/BM, D_/BN, E_), 256, SMEM_TG>>>(ph, We_o, pmoe, 0, D_, DH_, 1, 0, 1);
    add_ln_kernel<<<NTOK, 256>>>(px1, pmoe, ln2g, ln2b, nullptr, px2);

    // ---- final linear ----
    tgemm(px2, lin_w, plin, NTOK, D_, D_);
    add_ln_kernel<<<NTOK, 256>>>(px2, plin, ln3g, ln3b, lin_b, out);
}

// round 5
// speedup vs baseline: 6.1720x; 1.9542x over previous
#include <cuda_runtime.h>
#include <cstdint>
#include <math.h>

#define D_    1024
#define DL_   1024
#define DH_   2048
#define NL_   64
#define H_    16
#define E_    8
#define B_    2
#define T_    2048
#define NTOK  (B_*T_)      /* 4096 */
#define HALF_ 32
#define SLOTS (NTOK*2)     /* 8192 */

// ----------------------------- scratch (device globals, no allocs) -----------
__device__ float g_Lq[NL_*DL_];
__device__ float g_K [NTOK*DL_];
__device__ float g_V [NTOK*DL_];
__device__ float g_Qx[NTOK*DL_];
__device__ float g_z [B_*NL_*DL_];
__device__ float g_Ql[B_*NL_*DL_];
__device__ float g_Kl[B_*NL_*DL_];
__device__ float g_Vl[B_*NL_*DL_];
__device__ float g_z2[B_*NL_*DL_];
__device__ float g_Kz[B_*NL_*DL_];
__device__ float g_Vz[B_*NL_*DL_];
__device__ float g_xl[NTOK*DL_];
__device__ float g_attnout[NTOK*D_];
__device__ float g_x1[NTOK*D_];
__device__ float g_moe[NTOK*D_];
__device__ float g_x2[NTOK*D_];
__device__ float g_lin[NTOK*D_];
__device__ float g_h [(size_t)SLOTS*DH_];
__device__ float g_hb[(size_t)SLOTS*DH_];
__device__ int   g_counts[E_];
__device__ int   g_offsets[E_];
__device__ int   g_cursor[E_];
__device__ int   g_slot_token[SLOTS];
__device__ float g_slot_gate[SLOTS];
__device__ int   g_topi[NTOK*2];
__device__ float g_gate[NTOK*2];

// ----------------------------- tf32 helpers ----------------------------------
__device__ __forceinline__ uint32_t f2tf(float f) {
    uint32_t u; asm("cvt.rna.tf32.f32 %0, %1;" : "=r"(u) : "f"(f)); return u;
}
__device__ __forceinline__ uint32_t f2tf_bits(uint32_t b) {
    uint32_t u; asm("cvt.rna.tf32.f32 %0, %1;" : "=r"(u) : "f"(__uint_as_float(b))); return u;
}
__device__ __forceinline__ void mma_tf32(float* d, const uint32_t* a, const uint32_t* b) {
    asm volatile("mma.sync.aligned.m16n8k8.row.col.f32.tf32.tf32.f32 "
        "{%0,%1,%2,%3}, {%4,%5,%6,%7}, {%8,%9}, {%0,%1,%2,%3};\n"
        : "+f"(d[0]), "+f"(d[1]), "+f"(d[2]), "+f"(d[3])
        : "r"(a[0]), "r"(a[1]), "r"(a[2]), "r"(a[3]), "r"(b[0]), "r"(b[1]));
}
__device__ __forceinline__ void ldmatrix4(uint32_t* r, uint32_t addr) {
    asm volatile("ldmatrix.sync.aligned.m8n8.x4.shared.b16 {%0,%1,%2,%3}, [%4];"
        : "=r"(r[0]), "=r"(r[1]), "=r"(r[2]), "=r"(r[3]) : "r"(addr));
}
__device__ __forceinline__ void cpasync16(uint32_t dst, const void* src) {
    asm volatile("cp.async.cg.shared.global [%0], [%1], 16;\n" :: "r"(dst), "l"(src));
}
__device__ __forceinline__ void cpcommit() {
    asm volatile("cp.async.commit_group;\n" ::: "memory");
}
__device__ __forceinline__ void cpwait2() {
    asm volatile("cp.async.wait_group 2;\n" ::: "memory");
}

#define BM 128
#define BN 256
#define BK 32
#define ASTR 36
#define BSTR 264
#define AWORDS (BM*ASTR)
#define BWORDS (BK*BSTR)
#define STAGE_WORDS (AWORDS+BWORDS)
#define STAGES 3
#define SMEM_TG (STAGES*STAGE_WORDS*4)

// C[M,N] = A[M,K] @ B[K,N], tf32 tensor cores, fp32 accumulate.
// expertMode: M=g_counts[z], base=g_offsets[z], B += z*K*N.
// gatherA: A row = g_slot_token[slot]; scatterC: C[token] += gate*acc (atomic).
// splitK (non-expert only): blockIdx.z = k-chunk; atomic accumulate into zeroed C.
__global__ void __launch_bounds__(256) tgemm_kernel(
    const float* __restrict__ A, const float* __restrict__ Bm, float* __restrict__ C,
    int M, int N, int K, int expertMode, int gatherA, int scatterC, int splitK)
{
    extern __shared__ float dsm[];
    __shared__ int   rIn[BM];
    __shared__ int   rOut[BM];
    __shared__ float rGate[BM];

    const int tid = threadIdx.x;
    int base = 0;
    int kOff = 0, Kloc = K;
    if (expertMode) {
        int e = blockIdx.z;
        M = g_counts[e];
        base = g_offsets[e];
        Bm += (size_t)e * K * N;
    } else if (splitK > 1) {
        Kloc = K / splitK;
        kOff = blockIdx.z * Kloc;
    }
    const int tile_m = blockIdx.x * BM;
    if (tile_m >= M) return;
    const int tile_n = blockIdx.y * BN;

    if (tid < BM) {
        int m = tile_m + tid;
        if (m < M) {
            int slot = base + m;
            rIn[tid]   = gatherA  ? g_slot_token[slot] : (expertMode ? slot : m);
            rOut[tid]  = scatterC ? g_slot_token[slot] : (expertMode ? slot : m);
            rGate[tid] = scatterC ? g_slot_gate[slot] : 1.f;
        } else { rIn[tid] = 0; rOut[tid] = -1; rGate[tid] = 0.f; }
    }
    __syncthreads();

    const uint32_t smem_u32 = (uint32_t)__cvta_generic_to_shared(dsm);

    const int lane = tid & 31;
    const int wid  = tid >> 5;
    const int wm = (wid >> 2) * 64;
    const int wn = (wid & 3) * 64;
    const int gid = lane >> 2, tig = lane & 3;

    const int lj = lane >> 3, lr = lane & 7;
    const uint32_t aLanePart = ((uint32_t)(wm + (lj & 1) * 8 + lr) * ASTR + (lj >> 1) * 4) * 4u;

    const int a_row = tid >> 3;
    const int a_kc  = (tid & 7) * 4;
    const int b_row = tid >> 6;
    const int b_nc  = (tid & 63) * 4;

    const int nkt = Kloc / BK;

    auto issue = [&](int kt) {
        const int s = kt % STAGES;
        const int k0 = kOff + kt * BK;
        const uint32_t aBase = smem_u32 + s * (STAGE_WORDS * 4);
        const uint32_t bBase = aBase + AWORDS * 4;
        #pragma unroll
        for (int i = 0; i < 4; i++) {
            int row = a_row + i * 32;
            int ar = rIn[row];
            cpasync16(aBase + ((uint32_t)row * ASTR + a_kc) * 4u,
                      A + (size_t)ar * K + k0 + a_kc);
        }
        #pragma unroll
        for (int i = 0; i < 8; i++) {
            int row = b_row + i * 4;
            cpasync16(bBase + ((uint32_t)row * BSTR + b_nc) * 4u,
                      Bm + (size_t)(k0 + row) * N + tile_n + b_nc);
        }
    };

    float acc[4][8][4];
    #pragma unroll
    for (int i = 0; i < 4; i++)
        #pragma unroll
        for (int j = 0; j < 8; j++)
            #pragma unroll
            for (int q = 0; q < 4; q++) acc[i][j][q] = 0.f;

    issue(0); cpcommit();
    if (nkt > 1) issue(1); cpcommit();

    for (int kt = 0; kt < nkt; kt++) {
        if (kt + 2 < nkt) issue(kt + 2);
        cpcommit();
        cpwait2();
        __syncthreads();

        const int s = kt % STAGES;
        const uint32_t aBase = smem_u32 + s * (STAGE_WORDS * 4) + aLanePart;
        const float* Bs = dsm + s * STAGE_WORDS + AWORDS;

        #pragma unroll
        for (int ks = 0; ks < 4; ks++) {
            uint32_t af[4][4];
            #pragma unroll
            for (int mi = 0; mi < 4; mi++) {
                ldmatrix4(af[mi], aBase + mi * (16 * ASTR * 4) + ks * 32);
                #pragma unroll
                for (int q = 0; q < 4; q++) af[mi][q] = f2tf_bits(af[mi][q]);
            }
            uint32_t bf[8][2];
            #pragma unroll
            for (int ni = 0; ni < 8; ni++) {
                int idx = (ks * 8 + tig) * BSTR + wn + ni * 8 + gid;
                bf[ni][0] = f2tf(Bs[idx]);
                bf[ni][1] = f2tf(Bs[idx + 4 * BSTR]);
            }
            #pragma unroll
            for (int mi = 0; mi < 4; mi++)
                #pragma unroll
                for (int ni = 0; ni < 8; ni++)
                    mma_tf32(acc[mi][ni], af[mi], bf[ni]);
        }
        __syncthreads();
    }

    const bool atom = (scatterC != 0) || (splitK > 1);
    #pragma unroll
    for (int mi = 0; mi < 4; mi++) {
        int rl0 = wm + mi * 16 + gid;
        int rl1 = rl0 + 8;
        int o0 = rOut[rl0], o1 = rOut[rl1];
        float g0 = rGate[rl0], g1 = rGate[rl1];
        #pragma unroll
        for (int ni = 0; ni < 8; ni++) {
            int c = tile_n + wn + ni * 8 + tig * 2;
            if (atom) {
                if (o0 >= 0) {
                    atomicAdd(&C[(size_t)o0 * N + c],     g0 * acc[mi][ni][0]);
                    atomicAdd(&C[(size_t)o0 * N + c + 1], g0 * acc[mi][ni][1]);
                }
                if (o1 >= 0) {
                    atomicAdd(&C[(size_t)o1 * N + c],     g1 * acc[mi][ni][2]);
                    atomicAdd(&C[(size_t)o1 * N + c + 1], g1 * acc[mi][ni][3]);
                }
            } else {
                if (o0 >= 0) *(float2*)&C[(size_t)o0 * N + c] = make_float2(acc[mi][ni][0], acc[mi][ni][1]);
                if (o1 >= 0) *(float2*)&C[(size_t)o1 * N + c] = make_float2(acc[mi][ni][2], acc[mi][ni][3]);
            }
        }
    }
}

// ----------------------------- tiled attention --------------------------------
// One block per (64-query tile, head, batch). 64 keys (dh=64). Q/K/V staged in
// smem; scores + softmax + PV in-block. causal: mask key j > query index.
#define APAD 68
#define ATTN_SMEM (3*64*APAD*4)
__global__ void __launch_bounds__(256) attn_tile_kernel(
    const float* __restrict__ Q, int qbs,
    const float* __restrict__ Ksrc, const float* __restrict__ Vsrc, int kbs,
    float* __restrict__ Out, int obs, int causal)
{
    extern __shared__ float sm[];
    float* Ks = sm;
    float* Vs = sm + 64 * APAD;
    float* Ws = sm + 2 * 64 * APAD;   // Q tile first, then reused for softmax probs

    const int tid = threadIdx.x;
    const int h = blockIdx.y, b = blockIdx.z;
    const int qtile = blockIdx.x * 64;

    // stage K, V, Q (into Ws)
    {
        int row = tid >> 2;
        int c0 = (tid & 3) * 16;
        const float* kp = Ksrc + ((size_t)(b * kbs + row)) * DL_ + h * 64 + c0;
        const float* vp = Vsrc + ((size_t)(b * kbs + row)) * DL_ + h * 64 + c0;
        const float* qp = Q    + ((size_t)(b * qbs + qtile + row)) * DL_ + h * 64 + c0;
        #pragma unroll
        for (int j = 0; j < 4; j++) {
            *(float4*)&Ks[row * APAD + c0 + 4*j] = __ldg((const float4*)kp + j);
            *(float4*)&Vs[row * APAD + c0 + 4*j] = __ldg((const float4*)vp + j);
            *(float4*)&Ws[row * APAD + c0 + 4*j] = __ldg((const float4*)qp + j);
        }
    }
    __syncthreads();

    const int ty = tid >> 4, tx = tid & 15;
    const int q0 = ty * 4, j0 = tx * 4;

    // scores: acc[i][kk] = dot(Q[q0+i], K[j0+kk]) / 8
    float acc[4][4] = {};
    #pragma unroll
    for (int d4 = 0; d4 < 16; d4++) {
        float4 k4[4];
        #pragma unroll
        for (int kk = 0; kk < 4; kk++) k4[kk] = *(float4*)&Ks[(j0 + kk) * APAD + d4 * 4];
        #pragma unroll
        for (int i = 0; i < 4; i++) {
            float4 q4 = *(float4*)&Ws[(q0 + i) * APAD + d4 * 4];
            #pragma unroll
            for (int kk = 0; kk < 4; kk++)
                acc[i][kk] += q4.x * k4[kk].x + q4.y * k4[kk].y + q4.z * k4[kk].z + q4.w * k4[kk].w;
        }
    }
    #pragma unroll
    for (int i = 0; i < 4; i++)
        #pragma unroll
        for (int kk = 0; kk < 4; kk++) {
            float s = acc[i][kk] * 0.125f;
            if (causal && (j0 + kk > qtile + q0 + i)) s = -1e30f;
            acc[i][kk] = s;
        }
    __syncthreads();   // all Q reads done; Ws can be overwritten

    // softmax per query row (16 tx lanes hold 4 cols each; reduce within half-warp)
    #pragma unroll
    for (int i = 0; i < 4; i++) {
        float m = fmaxf(fmaxf(acc[i][0], acc[i][1]), fmaxf(acc[i][2], acc[i][3]));
        #pragma unroll
        for (int off = 1; off < 16; off <<= 1) m = fmaxf(m, __shfl_xor_sync(0xffffffffu, m, off));
        float e[4], sum = 0.f;
        #pragma unroll
        for (int kk = 0; kk < 4; kk++) { e[kk] = __expf(acc[i][kk] - m); sum += e[kk]; }
        #pragma unroll
        for (int off = 1; off < 16; off <<= 1) sum += __shfl_xor_sync(0xffffffffu, sum, off);
        float inv = 1.f / sum;
        #pragma unroll
        for (int kk = 0; kk < 4; kk++) Ws[(q0 + i) * APAD + j0 + kk] = e[kk] * inv;
    }
    __syncthreads();

    // output: O[q][d] = sum_j W[q][j] * V[j][d]
    float o[4][4] = {};
    const int d0 = tx * 4;
    for (int j = 0; j < 64; j++) {
        float4 v4 = *(float4*)&Vs[j * APAD + d0];
        #pragma unroll
        for (int i = 0; i < 4; i++) {
            float w = Ws[(q0 + i) * APAD + j];
            o[i][0] += w * v4.x; o[i][1] += w * v4.y;
            o[i][2] += w * v4.z; o[i][3] += w * v4.w;
        }
    }
    #pragma unroll
    for (int i = 0; i < 4; i++) {
        float4 r = make_float4(o[i][0], o[i][1], o[i][2], o[i][3]);
        *(float4*)&Out[((size_t)(b * obs + qtile + q0 + i)) * DL_ + h * 64 + d0] = r;
    }
}

// ----------------------------- SwiGLU elementwise ----------------------------
__global__ void swiglu_kernel(float4* __restrict__ ha, const float4* __restrict__ hb) {
    size_t i = (size_t)blockIdx.x * blockDim.x + threadIdx.x;
    float4 a = ha[i];
    float4 b = hb[i];
    a.x *= b.x / (1.f + __expf(-b.x));
    a.y *= b.y / (1.f + __expf(-b.y));
    a.z *= b.z / (1.f + __expf(-b.z));
    a.w *= b.w / (1.f + __expf(-b.w));
    ha[i] = a;
}

// ----------------------------- RoPE ------------------------------------------
__global__ void rope_kernel(float* __restrict__ buf, const float* __restrict__ cosb,
                            const float* __restrict__ sinb) {
    int idx = blockIdx.x * blockDim.x + threadIdx.x;
    if (idx >= NTOK * H_ * HALF_) return;
    int j = idx & 31;
    int h = (idx >> 5) & 15;
    int r = idx >> 9;
    int t = r % T_;
    float c = cosb[t * HALF_ + j];
    float s = sinb[t * HALF_ + j];
    size_t base = (size_t)r * DL_ + h * 64 + 2 * j;
    float x1 = buf[base], x2 = buf[base + 1];
    buf[base]     = x1 * c - x2 * s;
    buf[base + 1] = x1 * s + x2 * c;
}

// ----------------------------- LayerNorm(+residual+bias) ---------------------
__global__ void add_ln_kernel(const float* __restrict__ src, const float* __restrict__ addv,
                              const float* __restrict__ g, const float* __restrict__ bt,
                              const float* __restrict__ bias, float* __restrict__ out) {
    int row = blockIdx.x;
    int tid = threadIdx.x;
    const float* x = src + (size_t)row * D_;
    float v[4];
    #pragma unroll
    for (int i = 0; i < 4; i++) v[i] = x[tid + i * 256];
    __shared__ float red[256];
    float s = v[0] + v[1] + v[2] + v[3];
    red[tid] = s; __syncthreads();
    for (int o = 128; o > 0; o >>= 1) { if (tid < o) red[tid] += red[tid + o]; __syncthreads(); }
    float mean = red[0] * (1.f / 1024.f);
    __syncthreads();
    float d0 = v[0]-mean, d1 = v[1]-mean, d2 = v[2]-mean, d3 = v[3]-mean;
    red[tid] = d0*d0 + d1*d1 + d2*d2 + d3*d3; __syncthreads();
    for (int o = 128; o > 0; o >>= 1) { if (tid < o) red[tid] += red[tid + o]; __syncthreads(); }
    float stdv = sqrtf(red[0] * (1.f / 1023.f));
    float inv = 1.f / (stdv + 1e-6f);
    #pragma unroll
    for (int i = 0; i < 4; i++) {
        int c = tid + i * 256;
        float r = g[c] * (v[i] - mean) * inv + bt[c] + addv[(size_t)row * D_ + c];
        if (bias) r += bias[c];
        out[(size_t)row * D_ + c] = r;
    }
}

// ----------------------------- router + routing ------------------------------
__global__ void router_kernel(const float* __restrict__ X, const float* __restrict__ Wr,
                              const float* __restrict__ br) {
    int n = blockIdx.x;
    int tid = threadIdx.x;
    int wrp = tid >> 5, lane = tid & 31;
    const float* xr = X + (size_t)n * D_;
    float p = 0.f;
    for (int d = lane; d < D_; d += 32) p += xr[d] * Wr[d * E_ + wrp];
    #pragma unroll
    for (int o = 16; o > 0; o >>= 1) p += __shfl_down_sync(0xffffffffu, p, o);
    __shared__ float lg[E_];
    if (lane == 0) lg[wrp] = p + br[wrp];
    __syncthreads();
    if (tid == 0) {
        int i0 = 0; float v0 = lg[0];
        for (int e = 1; e < E_; e++) if (lg[e] > v0) { v0 = lg[e]; i0 = e; }
        int i1 = -1; float v1 = -1e30f;
        for (int e = 0; e < E_; e++) if (e != i0 && lg[e] > v1) { v1 = lg[e]; i1 = e; }
        float e1 = expf(v1 - v0);
        float p0 = 1.f / (1.f + e1);
        float p1 = e1 / (1.f + e1);
        g_topi[n*2] = i0;  g_topi[n*2+1] = i1;
        g_gate[n*2] = p0;  g_gate[n*2+1] = p1;
        atomicAdd(&g_counts[i0], 1);
        atomicAdd(&g_counts[i1], 1);
    }
}

__global__ void scan_kernel() {
    if (threadIdx.x == 0 && blockIdx.x == 0) {
        int acc = 0;
        for (int e = 0; e < E_; e++) { g_offsets[e] = acc; acc += g_counts[e]; g_cursor[e] = 0; }
    }
}

__global__ void scatter_kernel() {
    int n = blockIdx.x * blockDim.x + threadIdx.x;
    if (n >= NTOK) return;
    #pragma unroll
    for (int k = 0; k < 2; k++) {
        int e = g_topi[n*2 + k];
        int pos = atomicAdd(&g_cursor[e], 1);
        int s = g_offsets[e] + pos;
        g_slot_token[s] = n;
        g_slot_gate[s]  = g_gate[n*2 + k];
    }
}

// ----------------------------- host ------------------------------------------
static inline void tgemm(const float* A, const float* B, float* C, int M, int N, int K) {
    dim3 grid((M + BM - 1) / BM, N / BN, 1);
    tgemm_kernel<<<grid, 256, SMEM_TG>>>(A, B, C, M, N, K, 0, 0, 0, 1);
}
// split-K GEMM for small M: C must be zeroed first
static inline void tgemm_sk(const float* A, const float* B, float* C, int M, int N, int K, int KS) {
    cudaMemsetAsync(C, 0, (size_t)M * N * sizeof(float), 0);
    dim3 grid((M + BM - 1) / BM, N / BN, KS);
    tgemm_kernel<<<grid, 256, SMEM_TG>>>(A, B, C, M, N, K, 0, 0, 0, KS);
}

extern "C" void kernel_launch(void* const* d_in, const int* in_sizes, int n_in,
                              void* d_out, int out_size) {
    const float* x        = (const float*)d_in[0];
    const float* cosb     = (const float*)d_in[1];
    const float* sinb     = (const float*)d_in[2];
    const float* ln1g     = (const float*)d_in[3];
    const float* ln1b     = (const float*)d_in[4];
    const float* ln2g     = (const float*)d_in[5];
    const float* ln2b     = (const float*)d_in[6];
    const float* ln3g     = (const float*)d_in[7];
    const float* ln3b     = (const float*)d_in[8];
    const float* Lat      = (const float*)d_in[9];
    const float* wq_lat   = (const float*)d_in[10];
    const float* wk_in    = (const float*)d_in[11];
    const float* wv_in    = (const float*)d_in[12];
    const float* wq_in    = (const float*)d_in[13];
    const float* wk_lat   = (const float*)d_in[14];
    const float* wv_lat   = (const float*)d_in[15];
    const float* w_out    = (const float*)d_in[16];
    const float* router_w = (const float*)d_in[17];
    const float* router_b = (const float*)d_in[18];
    const float* We_w     = (const float*)d_in[19];
    const float* We_v     = (const float*)d_in[20];
    const float* We_o     = (const float*)d_in[21];
    const float* lin_w    = (const float*)d_in[22];
    const float* lin_b    = (const float*)d_in[23];
    float* out = (float*)d_out;

    static bool attrDone = false;
    if (!attrDone) {
        cudaFuncSetAttribute(tgemm_kernel, cudaFuncAttributeMaxDynamicSharedMemorySize, SMEM_TG);
        cudaFuncSetAttribute(attn_tile_kernel, cudaFuncAttributeMaxDynamicSharedMemorySize, ATTN_SMEM);
        attrDone = true;
    }

    float *pLq, *pK, *pV, *pQx, *pz, *pQl, *pKl, *pVl, *pz2, *pKz, *pVz;
    float *pxl, *pattn, *px1, *pmoe, *px2, *plin, *ph, *phb;
    int *pcounts;
    cudaGetSymbolAddress((void**)&pLq,  g_Lq);
    cudaGetSymbolAddress((void**)&pK,   g_K);
    cudaGetSymbolAddress((void**)&pV,   g_V);
    cudaGetSymbolAddress((void**)&pQx,  g_Qx);
    cudaGetSymbolAddress((void**)&pz,   g_z);
    cudaGetSymbolAddress((void**)&pQl,  g_Ql);
    cudaGetSymbolAddress((void**)&pKl,  g_Kl);
    cudaGetSymbolAddress((void**)&pVl,  g_Vl);
    cudaGetSymbolAddress((void**)&pz2,  g_z2);
    cudaGetSymbolAddress((void**)&pKz,  g_Kz);
    cudaGetSymbolAddress((void**)&pVz,  g_Vz);
    cudaGetSymbolAddress((void**)&pxl,  g_xl);
    cudaGetSymbolAddress((void**)&pattn,g_attnout);
    cudaGetSymbolAddress((void**)&px1,  g_x1);
    cudaGetSymbolAddress((void**)&pmoe, g_moe);
    cudaGetSymbolAddress((void**)&px2,  g_x2);
    cudaGetSymbolAddress((void**)&plin, g_lin);
    cudaGetSymbolAddress((void**)&ph,   g_h);
    cudaGetSymbolAddress((void**)&phb,  g_hb);
    cudaGetSymbolAddress((void**)&pcounts, g_counts);

    // ---- attention pipeline ----
    tgemm_sk(Lat, wq_lat, pLq, NL_, DL_, DL_, 8);
    tgemm(x, wk_in, pK,  NTOK, DL_, D_);
    tgemm(x, wv_in, pV,  NTOK, DL_, D_);
    tgemm(x, wq_in, pQx, NTOK, DL_, D_);

    int nrope = NTOK * H_ * HALF_;
    rope_kernel<<<(nrope + 255) / 256, 256>>>(pK,  cosb, sinb);
    rope_kernel<<<(nrope + 255) / 256, 256>>>(pQx, cosb, sinb);

    attn_tile_kernel<<<dim3(1, H_, B_), 256, ATTN_SMEM>>>(pLq, 0, pK, pV, T_, pz, NL_, 1);
    tgemm_sk(pz, wq_lat, pQl, B_*NL_, DL_, DL_, 8);
    tgemm_sk(pz, wk_lat, pKl, B_*NL_, DL_, DL_, 8);
    tgemm_sk(pz, wv_lat, pVl, B_*NL_, DL_, DL_, 8);
    attn_tile_kernel<<<dim3(1, H_, B_), 256, ATTN_SMEM>>>(pQl, NL_, pKl, pVl, NL_, pz2, NL_, 0);
    tgemm_sk(pz2, wk_lat, pKz, B_*NL_, DL_, DL_, 8);
    tgemm_sk(pz2, wv_lat, pVz, B_*NL_, DL_, DL_, 8);
    attn_tile_kernel<<<dim3(T_/64, H_, B_), 256, ATTN_SMEM>>>(pQx, T_, pKz, pVz, NL_, pxl, T_, 0);

    tgemm(pxl, w_out, pattn, NTOK, D_, DL_);
    add_ln_kernel<<<NTOK, 256>>>(x, pattn, ln1g, ln1b, nullptr, px1);

    // ---- MoE (top-2 grouped GEMM, tf32) ----
    cudaMemsetAsync(pcounts, 0, E_ * sizeof(int), 0);
    router_kernel<<<NTOK, 256>>>(px1, router_w, router_b);
    scan_kernel<<<1, 32>>>();
    scatter_kernel<<<(NTOK + 255) / 256, 256>>>();

    tgemm_kernel<<<dim3(SLOTS/BM, DH_/BN, E_), 256, SMEM_TG>>>(px1, We_w, ph,  0, DH_, D_, 1, 1, 0, 1);
    tgemm_kernel<<<dim3(SLOTS/BM, DH_/BN, E_), 256, SMEM_TG>>>(px1, We_v, phb, 0, DH_, D_, 1, 1, 0, 1);
    swiglu_kernel<<<(SLOTS * (DH_/4)) / 256, 256>>>((float4*)ph, (const float4*)phb);

    cudaMemsetAsync(pmoe, 0, (size_t)NTOK * D_ * sizeof(float), 0);
    tgemm_kernel<<<dim3(SLOTS/BM, D_/BN, E_), 256, SMEM_TG>>>(ph, We_o, pmoe, 0, D_, DH_, 1, 0, 1, 1);
    add_ln_kernel<<<NTOK, 256>>>(px1, pmoe, ln2g, ln2b, nullptr, px2);

    // ---- final linear ----
    tgemm(px2, lin_w, plin, NTOK, D_, D_);
    add_ln_kernel<<<NTOK, 256>>>(px2, plin, ln3g, ln3b, lin_b, out);
}